// round 15
// baseline (speedup 1.0000x reference)
#include <cuda_runtime.h>
#include <cstdint>

#define D 128

// Scratch (static __device__ arrays — allocation-free per harness rules)
__device__ float g_A[100000 * D];   // variables @ W_msg[0:128]
__device__ float g_B[50000  * D];   // factors   @ W_msg[128:256] + b_msg

// ---------------------------------------------------------------------------
// f32x2 packed-FMA helpers (FFMA2 path, PTX-only on sm_103a)
// ---------------------------------------------------------------------------
__device__ __forceinline__ unsigned long long ffma2(unsigned long long a,
                                                    unsigned long long b,
                                                    unsigned long long c) {
    unsigned long long d;
    asm("fma.rn.f32x2 %0, %1, %2, %3;" : "=l"(d) : "l"(a), "l"(b), "l"(c));
    return d;
}

__device__ __forceinline__ float2 unpack2(unsigned long long v) {
    float2 r;
    asm("mov.b64 {%0, %1}, %2;" : "=f"(r.x), "=f"(r.y) : "l"(v));
    return r;
}

// ---------------------------------------------------------------------------
// C[M,128] = X[M,128] @ W[128,128] (+ bias)
// 128x128 block tile, BK=8, 256 threads, 8x8 microtile via f32x2 FMA.
// A-values stored duplicated in smem so LDS.128 yields (a,a,a',a') pairs.
// ---------------------------------------------------------------------------
__global__ __launch_bounds__(256, 2)
void gemm_k128(const float* __restrict__ X, const float* __restrict__ W,
               const float* __restrict__ bias, float* __restrict__ C, int M)
{
    __shared__ float As[8][256];   // As[k][2m] == As[k][2m+1] == X[row m][k]
    __shared__ float Bs[8][128];

    const int tid = threadIdx.x;
    const int blockRow = blockIdx.x * 128;
    const int tx = tid & 15;            // col group: 8 cols
    const int ty = tid >> 4;            // row group: 8 rows
    const int a_row = tid >> 1;
    const int a_k4  = (tid & 1) * 4;
    const int w_k = tid >> 5;
    const int w_n = (tid & 31) * 4;

    unsigned long long acc[8][4];
    #pragma unroll
    for (int i = 0; i < 8; i++)
        #pragma unroll
        for (int j = 0; j < 4; j++) acc[i][j] = 0ull;

    const int grow = blockRow + a_row;
    float4 aReg = (grow < M) ? *(const float4*)(X + (size_t)grow * D + a_k4)
                             : make_float4(0.f, 0.f, 0.f, 0.f);
    float4 wReg = *(const float4*)(W + (size_t)w_k * D + w_n);

    for (int kt = 0; kt < 16; ++kt) {
        *(float2*)&As[a_k4 + 0][2 * a_row] = make_float2(aReg.x, aReg.x);
        *(float2*)&As[a_k4 + 1][2 * a_row] = make_float2(aReg.y, aReg.y);
        *(float2*)&As[a_k4 + 2][2 * a_row] = make_float2(aReg.z, aReg.z);
        *(float2*)&As[a_k4 + 3][2 * a_row] = make_float2(aReg.w, aReg.w);
        *(float4*)&Bs[w_k][w_n] = wReg;
        __syncthreads();

        if (kt < 15) {
            const int kc = (kt + 1) * 8;
            aReg = (grow < M) ? *(const float4*)(X + (size_t)grow * D + kc + a_k4)
                              : make_float4(0.f, 0.f, 0.f, 0.f);
            wReg = *(const float4*)(W + (size_t)(kc + w_k) * D + w_n);
        }

        #pragma unroll
        for (int kk = 0; kk < 8; ++kk) {
            const ulonglong2* arow = (const ulonglong2*)(&As[kk][16 * ty]);
            ulonglong2 p0 = arow[0], p1 = arow[1], p2 = arow[2], p3 = arow[3];
            unsigned long long ap[8] = {p0.x, p0.y, p1.x, p1.y,
                                        p2.x, p2.y, p3.x, p3.y};
            const ulonglong2* brow = (const ulonglong2*)(&Bs[kk][8 * tx]);
            ulonglong2 q0 = brow[0], q1 = brow[1];
            unsigned long long bp[4] = {q0.x, q0.y, q1.x, q1.y};
            #pragma unroll
            for (int i = 0; i < 8; i++)
                #pragma unroll
                for (int j = 0; j < 4; j++)
                    acc[i][j] = ffma2(ap[i], bp[j], acc[i][j]);
        }
        __syncthreads();
    }

    #pragma unroll
    for (int i = 0; i < 8; i++) {
        const int row = blockRow + ty * 8 + i;
        if (row < M) {
            float* crow = C + (size_t)row * D + tx * 8;
            #pragma unroll
            for (int j = 0; j < 4; j++) {
                float2 v = unpack2(acc[i][j]);
                if (bias) {
                    v.x += bias[tx * 8 + 2 * j];
                    v.y += bias[tx * 8 + 2 * j + 1];
                }
                *(float2*)(crow + 2 * j) = v;
            }
        }
    }
}

// ---------------------------------------------------------------------------
// Combine: io <- vars + relu([vars, io] @ Wc[256,128] + bias)
// Same tiling, K=256 (first 16 k-tiles read vars, last 16 read io=aggr).
// In-place safe: every global read of io by a block precedes its epilogue
// writes, and blocks own disjoint row ranges.
// ---------------------------------------------------------------------------
__global__ __launch_bounds__(256, 2)
void combine_k256(const float* __restrict__ vars, const float* __restrict__ Wc,
                  const float* __restrict__ bias, float* __restrict__ io, int M)
{
    __shared__ float As[8][256];
    __shared__ float Bs[8][128];

    const int tid = threadIdx.x;
    const int blockRow = blockIdx.x * 128;
    const int tx = tid & 15;
    const int ty = tid >> 4;
    const int a_row = tid >> 1;
    const int a_k4  = (tid & 1) * 4;
    const int w_k = tid >> 5;
    const int w_n = (tid & 31) * 4;

    unsigned long long acc[8][4];
    #pragma unroll
    for (int i = 0; i < 8; i++)
        #pragma unroll
        for (int j = 0; j < 4; j++) acc[i][j] = 0ull;

    const int grow = blockRow + a_row;
    float4 aReg = (grow < M) ? *(const float4*)(vars + (size_t)grow * D + a_k4)
                             : make_float4(0.f, 0.f, 0.f, 0.f);
    float4 wReg = *(const float4*)(Wc + (size_t)w_k * D + w_n);

    for (int kt = 0; kt < 32; ++kt) {
        *(float2*)&As[a_k4 + 0][2 * a_row] = make_float2(aReg.x, aReg.x);
        *(float2*)&As[a_k4 + 1][2 * a_row] = make_float2(aReg.y, aReg.y);
        *(float2*)&As[a_k4 + 2][2 * a_row] = make_float2(aReg.z, aReg.z);
        *(float2*)&As[a_k4 + 3][2 * a_row] = make_float2(aReg.w, aReg.w);
        *(float4*)&Bs[w_k][w_n] = wReg;
        __syncthreads();

        if (kt < 31) {
            const int nk = kt + 1;
            const float* Xsrc = (nk < 16) ? vars : io;
            const int col = (nk & 15) * 8 + a_k4;
            aReg = (grow < M) ? *(const float4*)(Xsrc + (size_t)grow * D + col)
                              : make_float4(0.f, 0.f, 0.f, 0.f);
            wReg = *(const float4*)(Wc + (size_t)(nk * 8 + w_k) * D + w_n);
        }

        #pragma unroll
        for (int kk = 0; kk < 8; ++kk) {
            const ulonglong2* arow = (const ulonglong2*)(&As[kk][16 * ty]);
            ulonglong2 p0 = arow[0], p1 = arow[1], p2 = arow[2], p3 = arow[3];
            unsigned long long ap[8] = {p0.x, p0.y, p1.x, p1.y,
                                        p2.x, p2.y, p3.x, p3.y};
            const ulonglong2* brow = (const ulonglong2*)(&Bs[kk][8 * tx]);
            ulonglong2 q0 = brow[0], q1 = brow[1];
            unsigned long long bp[4] = {q0.x, q0.y, q1.x, q1.y};
            #pragma unroll
            for (int i = 0; i < 8; i++)
                #pragma unroll
                for (int j = 0; j < 4; j++)
                    acc[i][j] = ffma2(ap[i], bp[j], acc[i][j]);
        }
        __syncthreads();
    }

    #pragma unroll
    for (int i = 0; i < 8; i++) {
        const int row = blockRow + ty * 8 + i;
        if (row < M) {
            const int colbase = tx * 8;
            float* orow = io + (size_t)row * D + colbase;
            const float* vrow = vars + (size_t)row * D + colbase;
            #pragma unroll
            for (int j = 0; j < 4; j++) {
                float2 v = unpack2(acc[i][j]);
                float2 res;
                res.x = vrow[2 * j]     + fmaxf(v.x + bias[colbase + 2 * j],     0.f);
                res.y = vrow[2 * j + 1] + fmaxf(v.y + bias[colbase + 2 * j + 1], 0.f);
                *(float2*)(orow + 2 * j) = res;
            }
        }
    }
}

// ---------------------------------------------------------------------------
// Zero d_out (it is poisoned to 0xAA before timing)
// ---------------------------------------------------------------------------
__global__ void zero_kernel(float4* __restrict__ out, int n4)
{
    int i = blockIdx.x * blockDim.x + threadIdx.x;
    if (i < n4) out[i] = make_float4(0.f, 0.f, 0.f, 0.f);
}

// ---------------------------------------------------------------------------
// Edge phase: out[v] += relu(A[v] + B[f])  (one warp per edge, float4 lanes,
// vectorized red.global.add.v4.f32 scatter)
// ---------------------------------------------------------------------------
__global__ __launch_bounds__(256)
void edge_kernel(const int* __restrict__ v_to_f, const int* __restrict__ f_to_v,
                 const float* __restrict__ A, const float* __restrict__ B,
                 float* __restrict__ out, int E)
{
    const int gw = (int)((blockIdx.x * (unsigned)blockDim.x + threadIdx.x) >> 5);
    const int lane = threadIdx.x & 31;
    if (gw >= E) return;

    const int v = __ldg(v_to_f + gw);
    const int f = __ldg(f_to_v + gw);

    const float4 av = *(const float4*)(A + (size_t)v * D + lane * 4);
    const float4 bv = *(const float4*)(B + (size_t)f * D + lane * 4);

    const float x = fmaxf(av.x + bv.x, 0.f);
    const float y = fmaxf(av.y + bv.y, 0.f);
    const float z = fmaxf(av.z + bv.z, 0.f);
    const float w = fmaxf(av.w + bv.w, 0.f);

    float* o = out + (size_t)v * D + lane * 4;
    asm volatile("red.global.add.v4.f32 [%0], {%1, %2, %3, %4};"
                 :: "l"(o), "f"(x), "f"(y), "f"(z), "f"(w) : "memory");
}

// ---------------------------------------------------------------------------
// Launch
// ---------------------------------------------------------------------------
extern "C" void kernel_launch(void* const* d_in, const int* in_sizes, int n_in,
                              void* d_out, int out_size)
{
    const float* variables = (const float*)d_in[0];
    const float* factors   = (const float*)d_in[1];
    const int*   v_to_f    = (const int*)d_in[2];
    const int*   f_to_v    = (const int*)d_in[3];
    // d_in[4] = edge_attr: forward pass uses zeros_like(edge_attr) -> unused
    const float* W_msg     = (const float*)d_in[5];   // [257,128], row 256 dead
    const float* b_msg     = (const float*)d_in[6];   // [128]
    const float* W_comb    = (const float*)d_in[7];   // [256,128]
    const float* b_comb    = (const float*)d_in[8];   // [128]
    float* out = (float*)d_out;

    const int M_vars = in_sizes[0] / D;   // 100000
    const int M_fact = in_sizes[1] / D;   // 50000
    const int E      = in_sizes[2];       // 1000000

    float* gA = nullptr;
    float* gB = nullptr;
    cudaGetSymbolAddress((void**)&gA, g_A);
    cudaGetSymbolAddress((void**)&gB, g_B);

    // A = variables @ W1;  B = factors @ W2 + b_msg (bias folded once per edge)
    gemm_k128<<<(M_vars + 127) / 128, 256>>>(variables, W_msg, nullptr, gA, M_vars);
    gemm_k128<<<(M_fact + 127) / 128, 256>>>(factors, W_msg + D * D, b_msg, gB, M_fact);

    // aggr accumulates directly into d_out
    const int n4 = out_size / 4;
    zero_kernel<<<(n4 + 255) / 256, 256>>>((float4*)out, n4);
    edge_kernel<<<(E + 7) / 8, 256>>>(v_to_f, f_to_v, gA, gB, out, E);

    // out = vars + relu([vars, aggr] @ W_comb + b_comb), in-place over aggr
    combine_k256<<<(M_vars + 127) / 128, 256>>>(variables, W_comb, b_comb, out, M_vars);
}

// round 17
// speedup vs baseline: 1.2071x; 1.2071x over previous
#include <cuda_runtime.h>
#include <cstdint>

#define D 128

// ---------------------------------------------------------------------------
// Static device scratch (allocation-free per harness rules)
// ---------------------------------------------------------------------------
__device__ float g_A[100000 * D];      // variables @ W_msg[0:128]
__device__ float g_B[50000  * D];      // factors   @ W_msg[128:256] + b_msg
__device__ float g_Wimg[4 * 16384];    // fragment-ordered tf32 images: W1,W2,Wc0,Wc1
__device__ int   g_rowptr[100001];
__device__ int   g_cursor[100000];
__device__ int   g_col[1000000];

static __device__ __forceinline__ float to_tf32(float x) {
    float y; asm("cvt.rna.tf32.f32 %0, %1;" : "=f"(y) : "f"(x)); return y;
}

// m16n8k8 tf32 MMA (sm_80+ PTX — no sm_103a-only features)
static __device__ __forceinline__ void mma_tf32(float* c, const uint4 a, const uint2 b) {
    asm volatile("mma.sync.aligned.m16n8k8.row.col.f32.tf32.tf32.f32 "
                 "{%0,%1,%2,%3}, {%4,%5,%6,%7}, {%8,%9}, {%0,%1,%2,%3};"
                 : "+f"(c[0]), "+f"(c[1]), "+f"(c[2]), "+f"(c[3])
                 : "r"(a.x), "r"(a.y), "r"(a.z), "r"(a.w), "r"(b.x), "r"(b.y));
}

// ---------------------------------------------------------------------------
// prep_weights: fragment-ordered tf32 images of B^T.
// Image layout: idx = ((ntile*16 + kstep)*32 + lane)*2 + reg
//   b0: k = ks*8 + 0*4 + lane%4, n = nt*8 + lane/4 ; b1: k += 4
// img0 = W_msg[0:128], img1 = W_msg[128:256], img2/3 = W_comb halves.
// ---------------------------------------------------------------------------
__global__ void prep_weights(const float* __restrict__ W_msg,
                             const float* __restrict__ W_comb)
{
    int idx = blockIdx.x * blockDim.x + threadIdx.x;
    if (idx >= 4 * 16384) return;
    const int img  = idx >> 14;
    const int e    = idx & 16383;
    const int reg  = e & 1;
    const int lane = (e >> 1) & 31;
    const int ks   = (e >> 6) & 15;
    const int nt   = e >> 10;
    const int k = ks * 8 + reg * 4 + (lane & 3);
    const int n = nt * 8 + (lane >> 2);
    const float* W = (img < 2) ? W_msg  + (size_t)(img * 128) * D
                               : W_comb + (size_t)((img - 2) * 128) * D;
    g_Wimg[img * 16384 + e] = to_tf32(__ldg(W + (size_t)k * D + n));
}

// ---------------------------------------------------------------------------
// Fill a 128x128 A tile into fragment order:
//   float index = ((mtile*16 + kstep)*32 + lane)*4 + reg
//   a0:(r,c) a1:(r+8,c) a2:(r,c+4) a3:(r+8,c+4); r=lane/4 (m within 8), c=lane%4 (k)
// ---------------------------------------------------------------------------
static __device__ __forceinline__ void fill_A_frag(float* sA, const float* __restrict__ X,
                                                   int blockRow, int M, int tid)
{
    #pragma unroll
    for (int i = tid; i < 4096; i += 256) {
        const int m  = i >> 5;
        const int k4 = i & 31;
        const int grow = blockRow + m;
        float4 v = make_float4(0.f, 0.f, 0.f, 0.f);
        if (grow < M) v = __ldg((const float4*)(X + (size_t)grow * D + k4 * 4));
        v.x = to_tf32(v.x); v.y = to_tf32(v.y); v.z = to_tf32(v.z); v.w = to_tf32(v.w);
        const int mt = m >> 4, ml = m & 15;
        const int ks = k4 >> 1, kh = k4 & 1;
        const int regbase = (ml >= 8 ? 1 : 0) + (kh ? 2 : 0);
        float* dst = sA + ((mt * 16 + ks) * 32) * 4 + regbase;
        const int lane0 = (ml & 7) * 4;
        dst[(lane0 + 0) * 4] = v.x;
        dst[(lane0 + 1) * 4] = v.y;
        dst[(lane0 + 2) * 4] = v.z;
        dst[(lane0 + 3) * 4] = v.w;
    }
}

// ---------------------------------------------------------------------------
// gemm_mma: C[M,128] = X[M,128] @ W[128,128] (+ bias)
// 256 thr = 8 warps (2m x 4n), warp tile 64x32, BK=128 (single sync).
// smem: A frags 64KB + B image 64KB (dynamic).
// ---------------------------------------------------------------------------
__global__ __launch_bounds__(256, 1)
void gemm_mma(const float* __restrict__ X, const float* __restrict__ img,
              const float* __restrict__ bias, float* __restrict__ C, int M)
{
    extern __shared__ float smem[];
    float* sA = smem;            // 16384 floats
    float* sB = smem + 16384;    // 16384 floats

    const int tid = threadIdx.x, wid = tid >> 5, lane = tid & 31;
    const int blockRow = blockIdx.x * 128;

    #pragma unroll
    for (int i = tid; i < 4096; i += 256)
        ((float4*)sB)[i] = __ldg((const float4*)img + i);
    fill_A_frag(sA, X, blockRow, M, tid);
    __syncthreads();

    const int wm = (wid & 1) * 4;   // mtile base (16-row tiles)
    const int wn = (wid >> 1) * 4;  // ntile base (8-col tiles)

    float acc[4][4][4];
    #pragma unroll
    for (int i = 0; i < 4; i++)
        #pragma unroll
        for (int j = 0; j < 4; j++)
            #pragma unroll
            for (int q = 0; q < 4; q++) acc[i][j][q] = 0.f;

    #pragma unroll
    for (int ks = 0; ks < 16; ks++) {
        uint4 a[4]; uint2 b[4];
        #pragma unroll
        for (int i = 0; i < 4; i++)
            a[i] = ((const uint4*)sA)[((wm + i) * 16 + ks) * 32 + lane];
        #pragma unroll
        for (int j = 0; j < 4; j++)
            b[j] = ((const uint2*)sB)[((wn + j) * 16 + ks) * 32 + lane];
        #pragma unroll
        for (int i = 0; i < 4; i++)
            #pragma unroll
            for (int j = 0; j < 4; j++)
                mma_tf32(acc[i][j], a[i], b[j]);
    }

    #pragma unroll
    for (int j = 0; j < 4; j++) {
        const int col = (wn + j) * 8 + (lane & 3) * 2;
        float b0 = 0.f, b1 = 0.f;
        if (bias) { b0 = __ldg(bias + col); b1 = __ldg(bias + col + 1); }
        #pragma unroll
        for (int i = 0; i < 4; i++) {
            const int r0 = blockRow + (wm + i) * 16 + (lane >> 2);
            if (r0 < M)
                *(float2*)(C + (size_t)r0 * D + col) =
                    make_float2(acc[i][j][0] + b0, acc[i][j][1] + b1);
            if (r0 + 8 < M)
                *(float2*)(C + (size_t)(r0 + 8) * D + col) =
                    make_float2(acc[i][j][2] + b0, acc[i][j][3] + b1);
        }
    }
}

// ---------------------------------------------------------------------------
// combine_mma: io <- vars + relu(vars @ Wc0 + aggr @ Wc1 + bias)  (aggr = io)
// Two accumulating phases over one accumulator set; A smem refilled between.
// smem: A 64KB + B0 64KB + B1 64KB = 192KB.
// In-place safe: block reads all its io rows (phase-1 fill) before epilogue writes.
// ---------------------------------------------------------------------------
__global__ __launch_bounds__(256, 1)
void combine_mma(const float* __restrict__ vars, const float* __restrict__ img0,
                 const float* __restrict__ img1, const float* __restrict__ bias,
                 float* __restrict__ io, int M)
{
    extern __shared__ float smem[];
    float* sA  = smem;
    float* sB0 = smem + 16384;
    float* sB1 = smem + 2 * 16384;

    const int tid = threadIdx.x, wid = tid >> 5, lane = tid & 31;
    const int blockRow = blockIdx.x * 128;

    #pragma unroll
    for (int i = tid; i < 4096; i += 256) {
        ((float4*)sB0)[i] = __ldg((const float4*)img0 + i);
        ((float4*)sB1)[i] = __ldg((const float4*)img1 + i);
    }
    fill_A_frag(sA, vars, blockRow, M, tid);
    __syncthreads();

    const int wm = (wid & 1) * 4;
    const int wn = (wid >> 1) * 4;

    float acc[4][4][4];
    #pragma unroll
    for (int i = 0; i < 4; i++)
        #pragma unroll
        for (int j = 0; j < 4; j++)
            #pragma unroll
            for (int q = 0; q < 4; q++) acc[i][j][q] = 0.f;

    // Phase 0: vars @ Wc0
    #pragma unroll
    for (int ks = 0; ks < 16; ks++) {
        uint4 a[4]; uint2 b[4];
        #pragma unroll
        for (int i = 0; i < 4; i++)
            a[i] = ((const uint4*)sA)[((wm + i) * 16 + ks) * 32 + lane];
        #pragma unroll
        for (int j = 0; j < 4; j++)
            b[j] = ((const uint2*)sB0)[((wn + j) * 16 + ks) * 32 + lane];
        #pragma unroll
        for (int i = 0; i < 4; i++)
            #pragma unroll
            for (int j = 0; j < 4; j++)
                mma_tf32(acc[i][j], a[i], b[j]);
    }

    __syncthreads();                       // everyone done reading sA
    fill_A_frag(sA, io, blockRow, M, tid); // aggr tile
    __syncthreads();

    // Phase 1: += aggr @ Wc1
    #pragma unroll
    for (int ks = 0; ks < 16; ks++) {
        uint4 a[4]; uint2 b[4];
        #pragma unroll
        for (int i = 0; i < 4; i++)
            a[i] = ((const uint4*)sA)[((wm + i) * 16 + ks) * 32 + lane];
        #pragma unroll
        for (int j = 0; j < 4; j++)
            b[j] = ((const uint2*)sB1)[((wn + j) * 16 + ks) * 32 + lane];
        #pragma unroll
        for (int i = 0; i < 4; i++)
            #pragma unroll
            for (int j = 0; j < 4; j++)
                mma_tf32(acc[i][j], a[i], b[j]);
    }

    #pragma unroll
    for (int j = 0; j < 4; j++) {
        const int col = (wn + j) * 8 + (lane & 3) * 2;
        const float b0 = __ldg(bias + col);
        const float b1 = __ldg(bias + col + 1);
        #pragma unroll
        for (int i = 0; i < 4; i++) {
            const int r0 = blockRow + (wm + i) * 16 + (lane >> 2);
            if (r0 < M) {
                const float* vr = vars + (size_t)r0 * D + col;
                float2 res;
                res.x = vr[0] + fmaxf(acc[i][j][0] + b0, 0.f);
                res.y = vr[1] + fmaxf(acc[i][j][1] + b1, 0.f);
                *(float2*)(io + (size_t)r0 * D + col) = res;
            }
            if (r0 + 8 < M) {
                const float* vr = vars + (size_t)(r0 + 8) * D + col;
                float2 res;
                res.x = vr[0] + fmaxf(acc[i][j][2] + b0, 0.f);
                res.y = vr[1] + fmaxf(acc[i][j][3] + b1, 0.f);
                *(float2*)(io + (size_t)(r0 + 8) * D + col) = res;
            }
        }
    }
}

// ---------------------------------------------------------------------------
// CSR build: zero counts -> histogram -> single-block scan -> scatter
// ---------------------------------------------------------------------------
__global__ void zero_counts(int n) {
    int i = blockIdx.x * blockDim.x + threadIdx.x;
    if (i <= n) g_rowptr[i] = 0;
}

__global__ void hist_k(const int* __restrict__ v2f, int E) {
    int e = blockIdx.x * blockDim.x + threadIdx.x;
    if (e < E) atomicAdd(&g_rowptr[__ldg(v2f + e) + 1], 1);
}

__global__ __launch_bounds__(1024) void scan_k(int n) {
    __shared__ int wsum[32];
    const int tid = threadIdx.x;
    const int total = n + 1;
    const int chunk = (total + 1023) >> 10;
    const int s = tid * chunk;
    const int e = min(s + chunk, total);
    int sum = 0;
    for (int i = s; i < e; i++) sum += g_rowptr[i];
    const int lane = tid & 31, w = tid >> 5;
    int v = sum;
    #pragma unroll
    for (int o = 1; o < 32; o <<= 1) { int t = __shfl_up_sync(0xFFFFFFFFu, v, o); if (lane >= o) v += t; }
    if (lane == 31) wsum[w] = v;
    __syncthreads();
    if (w == 0) {
        int x = wsum[lane];
        #pragma unroll
        for (int o = 1; o < 32; o <<= 1) { int t = __shfl_up_sync(0xFFFFFFFFu, x, o); if (lane >= o) x += t; }
        wsum[lane] = x;
    }
    __syncthreads();
    int run = v - sum + (w > 0 ? wsum[w - 1] : 0);
    for (int i = s; i < e; i++) {
        run += g_rowptr[i];
        g_rowptr[i] = run;
        if (i < n) g_cursor[i] = run;
    }
}

__global__ void scatter_k(const int* __restrict__ v2f, const int* __restrict__ f2v, int E) {
    int e = blockIdx.x * blockDim.x + threadIdx.x;
    if (e < E) {
        int p = atomicAdd(&g_cursor[__ldg(v2f + e)], 1);
        g_col[p] = __ldg(f2v + e);
    }
}

// ---------------------------------------------------------------------------
// Aggregate: one warp per variable v: out[v] = sum_e relu(A[v] + B[col[e]])
// Streaming A/out, L2-resident B gathers, register accumulation, no atomics.
// ---------------------------------------------------------------------------
__global__ __launch_bounds__(256)
void aggregate_k(const float* __restrict__ A, const float* __restrict__ B,
                 float* __restrict__ out, int Nv)
{
    const int v = (int)((blockIdx.x * (unsigned)blockDim.x + threadIdx.x) >> 5);
    const int lane = threadIdx.x & 31;
    if (v >= Nv) return;

    const int beg = __ldg(&g_rowptr[v]);
    const int end = __ldg(&g_rowptr[v + 1]);
    const float4 a = __ldg((const float4*)(A + (size_t)v * D) + lane);
    float4 acc = make_float4(0.f, 0.f, 0.f, 0.f);

    int e = beg;
    for (; e + 2 <= end; e += 2) {
        const int f0 = __ldg(&g_col[e]);
        const int f1 = __ldg(&g_col[e + 1]);
        const float4 b0 = __ldg((const float4*)(B + (size_t)f0 * D) + lane);
        const float4 b1 = __ldg((const float4*)(B + (size_t)f1 * D) + lane);
        acc.x += fmaxf(a.x + b0.x, 0.f) + fmaxf(a.x + b1.x, 0.f);
        acc.y += fmaxf(a.y + b0.y, 0.f) + fmaxf(a.y + b1.y, 0.f);
        acc.z += fmaxf(a.z + b0.z, 0.f) + fmaxf(a.z + b1.z, 0.f);
        acc.w += fmaxf(a.w + b0.w, 0.f) + fmaxf(a.w + b1.w, 0.f);
    }
    if (e < end) {
        const int f0 = __ldg(&g_col[e]);
        const float4 b0 = __ldg((const float4*)(B + (size_t)f0 * D) + lane);
        acc.x += fmaxf(a.x + b0.x, 0.f);
        acc.y += fmaxf(a.y + b0.y, 0.f);
        acc.z += fmaxf(a.z + b0.z, 0.f);
        acc.w += fmaxf(a.w + b0.w, 0.f);
    }
    *(float4*)(out + (size_t)v * D + lane * 4) = acc;
}

// ---------------------------------------------------------------------------
// Launch
// ---------------------------------------------------------------------------
static const int SMEM_GEMM = 2 * 16384 * 4;   // 128 KB
static const int SMEM_COMB = 3 * 16384 * 4;   // 192 KB

extern "C" void kernel_launch(void* const* d_in, const int* in_sizes, int n_in,
                              void* d_out, int out_size)
{
    const float* variables = (const float*)d_in[0];
    const float* factors   = (const float*)d_in[1];
    const int*   v_to_f    = (const int*)d_in[2];
    const int*   f_to_v    = (const int*)d_in[3];
    // d_in[4] = edge_attr: forward uses zeros_like(edge_attr) -> unused, W_msg row 256 dead
    const float* W_msg     = (const float*)d_in[5];
    const float* b_msg     = (const float*)d_in[6];
    const float* W_comb    = (const float*)d_in[7];
    const float* b_comb    = (const float*)d_in[8];
    float* out = (float*)d_out;

    const int Mv = in_sizes[0] / D;   // 100000
    const int Mf = in_sizes[1] / D;   // 50000
    const int E  = in_sizes[2];       // 1000000

    float *gA = nullptr, *gB = nullptr, *gW = nullptr;
    cudaGetSymbolAddress((void**)&gA, g_A);
    cudaGetSymbolAddress((void**)&gB, g_B);
    cudaGetSymbolAddress((void**)&gW, g_Wimg);

    cudaFuncSetAttribute(gemm_mma, cudaFuncAttributeMaxDynamicSharedMemorySize, SMEM_GEMM);
    cudaFuncSetAttribute(combine_mma, cudaFuncAttributeMaxDynamicSharedMemorySize, SMEM_COMB);

    // 1) fragment-ordered tf32 weight images
    prep_weights<<<256, 256>>>(W_msg, W_comb);

    // 2) A = vars @ W1 ; B = factors @ W2 + b_msg
    gemm_mma<<<(Mv + 127) / 128, 256, SMEM_GEMM>>>(variables, gW,         nullptr, gA, Mv);
    gemm_mma<<<(Mf + 127) / 128, 256, SMEM_GEMM>>>(factors,   gW + 16384, b_msg,   gB, Mf);

    // 3) CSR by v (counting sort)
    zero_counts<<<(Mv + 256) / 256, 256>>>(Mv);
    hist_k<<<(E + 255) / 256, 256>>>(v_to_f, E);
    scan_k<<<1, 1024>>>(Mv);
    scatter_k<<<(E + 255) / 256, 256>>>(v_to_f, f_to_v, E);

    // 4) aggr (into d_out): one warp per variable, no atomics
    aggregate_k<<<((size_t)Mv * 32 + 255) / 256, 256>>>(gA, gB, out, Mv);

    // 5) out = vars + relu(vars @ Wc0 + aggr @ Wc1 + b_comb), in-place over aggr
    combine_mma<<<(Mv + 127) / 128, 256, SMEM_COMB>>>(variables, gW + 2 * 16384,
                                                      gW + 3 * 16384, b_comb, out, Mv);
}